// round 9
// baseline (speedup 1.0000x reference)
#include <cuda_runtime.h>
#include <math.h>

#define NN 8192
#define NE 131072

#define IS128 0.08838834764831845f
#define IS10  0.31622776601683794f
#define IS264 0.06154574548966636f
#define IS256 0.0625f
#define INV8  0.125f
#define INV_SQRT3 0.57735026918962576f
#define S3 (0.125f*0.57735026918962576f)

typedef unsigned long long ull;

// ---------------- scratch (no allocation allowed) ----------------
__device__ float g_us[NN*128];
__device__ float g_uv[NN*384];
__device__ float g_src[NN*128];
__device__ float g_tgt[NN*128];
__device__ float g_hA[(size_t)NE*64];
__device__ float g_density[NN];
__device__ float g_msgs[NN*256];
__device__ float g_msgv[NN*768];
__device__ int   g_cnt[NN];
__device__ int   g_cursor[NN];
__device__ int   g_list[NE];     // sorted position -> edge id
__device__ int   g_ssnd[NE];     // sorted position -> sender
__device__ int   g_srcv[NE];     // sorted position -> receiver

// k-pair-packed weights ({W[2k2][o], W[2k2+1][o]} per ull)
__device__ ull g_pWr0[132*64];
__device__ ull g_pWd0[132*64];
__device__ ull g_pW1 [32*64];
__device__ ull g_pW2 [32*64];
__device__ ull g_pWr3[32*512];
__device__ ull g_pW1s[128*256];
__device__ ull g_pWrs[64*256];
__device__ ull g_pWus[64*128];
__device__ ull g_pWss[64*128];

__device__ __forceinline__ float siluf(float x){ return x/(1.0f+expf(-x)); }
__device__ __forceinline__ float sigmf(float x){ return 1.0f/(1.0f+expf(-x)); }

__device__ __forceinline__ ull pk2(float lo, float hi){
    ull r; asm("mov.b64 %0, {%1,%2};" : "=l"(r) : "f"(lo), "f"(hi)); return r;
}
__device__ __forceinline__ void fma2(ull &d, ull a, ull b){
    asm("fma.rn.f32x2 %0, %1, %2, %0;" : "+l"(d) : "l"(a), "l"(b));
}
__device__ __forceinline__ float red2(ull v){
    float lo, hi; asm("mov.b64 {%0,%1}, %2;" : "=f"(lo), "=f"(hi) : "l"(v)); return lo+hi;
}

// ---------------- K0: zero accumulators + counters ----------------
__global__ void k0_zero(){
    int idx = blockIdx.x*blockDim.x + threadIdx.x;   // grid covers NN*768/4
    float4 z = make_float4(0.f,0.f,0.f,0.f);
    if (idx < NN*256/4) ((float4*)g_msgs)[idx] = z;
    if (idx < NN*768/4) ((float4*)g_msgv)[idx] = z;
    if (idx < NN/4)     ((float4*)g_density)[idx] = z;
    if (idx < NN)       g_cnt[idx] = 0;
}

// ---------------- weight pack: 9 matrices -> k-pair ull layout ----------------
__global__ void k_pack_all(
    const float* __restrict__ Wr0, const float* __restrict__ Wd0,
    const float* __restrict__ Wr1, const float* __restrict__ Wr2,
    const float* __restrict__ Wr3, const float* __restrict__ W1s,
    const float* __restrict__ Wrs, const float* __restrict__ Wus,
    const float* __restrict__ Wss)
{
    int idx = blockIdx.x*blockDim.x + threadIdx.x;
    const float* src; ull* dst; int N; int li;
    if      (idx < 8448)  { src=Wr0; dst=g_pWr0; N=64;  li=idx; }
    else if (idx < 16896) { src=Wd0; dst=g_pWd0; N=64;  li=idx-8448; }
    else if (idx < 18944) { src=Wr1; dst=g_pW1;  N=64;  li=idx-16896; }
    else if (idx < 20992) { src=Wr2; dst=g_pW2;  N=64;  li=idx-18944; }
    else if (idx < 37376) { src=Wr3; dst=g_pWr3; N=512; li=idx-20992; }
    else if (idx < 70144) { src=W1s; dst=g_pW1s; N=256; li=idx-37376; }
    else if (idx < 86528) { src=Wrs; dst=g_pWrs; N=256; li=idx-70144; }
    else if (idx < 94720) { src=Wus; dst=g_pWus; N=128; li=idx-86528; }
    else if (idx < 102912){ src=Wss; dst=g_pWss; N=128; li=idx-94720; }
    else return;
    int k2 = li / N, o = li - k2*N;
    dst[li] = pk2(src[(2*k2)*N+o], src[(2*k2+1)*N+o]);
}

// ---------------- sort: histogram / scan / fill ----------------
__global__ void k_hist(const int* __restrict__ rcv){
    int e = blockIdx.x*blockDim.x + threadIdx.x;
    if (e < NE) atomicAdd(&g_cnt[rcv[e]], 1);
}

__global__ __launch_bounds__(1024) void k_scan(){
    __shared__ int part[1024];
    int tid = threadIdx.x;
    int base = tid*8;
    int vals[8]; int sum=0;
    #pragma unroll
    for (int i=0;i<8;i++){ vals[i]=g_cnt[base+i]; sum+=vals[i]; }
    part[tid]=sum;
    __syncthreads();
    for (int d=1; d<1024; d<<=1){
        int v = (tid>=d) ? part[tid-d] : 0;
        __syncthreads();
        part[tid] += v;
        __syncthreads();
    }
    int run = part[tid]-sum;   // exclusive
    #pragma unroll
    for (int i=0;i<8;i++){ g_cursor[base+i]=run; run+=vals[i]; }
}

__global__ void k_fill(const int* __restrict__ snd, const int* __restrict__ rcv){
    int e = blockIdx.x*blockDim.x + threadIdx.x;
    if (e < NE){
        int r = rcv[e];
        int pos = atomicAdd(&g_cursor[r], 1);
        g_list[pos] = e;
        g_ssnd[pos] = snd[e];
        g_srcv[pos] = r;
    }
}

// ---------------- K1: node prep (sc, us, uv, src_e, tgt_e) ----------------
__global__ __launch_bounds__(128) void k1_node_prep(
    const float* __restrict__ node_attrs, const float* __restrict__ node_feats,
    const float* __restrict__ Wsv, const float* __restrict__ Wuv,
    const float* __restrict__ Wsrc, const float* __restrict__ Wtgt,
    float* __restrict__ out_sc)
{
    __shared__ float s8[8][128];
    __shared__ float v8[8][384];
    __shared__ float a8[8][10];
    int nb = blockIdx.x*8;
    int tid = threadIdx.x;
    for (int idx=tid; idx<8*512; idx+=128){
        int i = idx>>9, f = idx&511;
        float v = node_feats[(size_t)(nb+i)*512 + f];
        if (f<128) s8[i][f]=v; else v8[i][f-128]=v;
    }
    for (int idx=tid; idx<80; idx+=128)
        a8[idx/10][idx%10] = node_attrs[(size_t)(nb + idx/10)*10 + (idx%10)];
    __syncthreads();
    int w = tid;

    // scalar channels: packed f32x2 dot products
    {
        ull au[8], as_[8];
        #pragma unroll
        for (int i=0;i<8;i++){ au[i]=0ull; as_[i]=0ull; }
        for (int k2=0;k2<64;k2+=2){
            ull wu0=g_pWus[k2*128+w], wu1=g_pWus[(k2+1)*128+w];
            ull ws0=g_pWss[k2*128+w], ws1=g_pWss[(k2+1)*128+w];
            #pragma unroll
            for (int i=0;i<8;i++){
                const ull* sp = (const ull*)&s8[i][k2*2];
                fma2(au[i],  sp[0], wu0); fma2(au[i],  sp[1], wu1);
                fma2(as_[i], sp[0], ws0); fma2(as_[i], sp[1], ws1);
            }
        }
        #pragma unroll
        for (int i=0;i<8;i++){
            g_us[(nb+i)*128 + w] = red2(au[i])*IS128;
            out_sc[(size_t)(nb+i)*512 + w] = red2(as_[i])*IS128;
        }
    }

    // vector channels (strided, scalar)
    float acc1[8], acc2[8];
    for (int c=0;c<3;c++){
        #pragma unroll
        for (int i=0;i<8;i++){acc1[i]=0.f;acc2[i]=0.f;}
        for (int k=0;k<128;k++){
            float wu = Wuv[k*128+w], ws = Wsv[k*128+w];
            #pragma unroll
            for (int i=0;i<8;i++){ float vv=v8[i][k*3+c]; acc1[i]+=vv*wu; acc2[i]+=vv*ws; }
        }
        #pragma unroll
        for (int i=0;i<8;i++){
            g_uv[(nb+i)*384 + w*3 + c] = acc1[i]*IS128;
            out_sc[(size_t)(nb+i)*512 + 128 + w*3 + c] = acc2[i]*IS128;
        }
    }

    // attr embeddings
    #pragma unroll
    for (int i=0;i<8;i++){acc1[i]=0.f;acc2[i]=0.f;}
    for (int k=0;k<10;k++){
        float w1 = Wsrc[k*128+w], w2 = Wtgt[k*128+w];
        #pragma unroll
        for (int i=0;i<8;i++){ float av=a8[i][k]; acc1[i]+=av*w1; acc2[i]+=av*w2; }
    }
    #pragma unroll
    for (int i=0;i<8;i++){
        g_src[(nb+i)*128+w] = acc1[i]*IS10;
        g_tgt[(nb+i)*128+w] = acc2[i]*IS10;
    }
}

// ---------------- K2: edge layer0 + density (sorted edge order, f32x2) ------
__global__ __launch_bounds__(256) void k2_edge_l0(
    const float* __restrict__ edge_feats,
    const float* __restrict__ Wd1)
{
    __shared__ float ef[32][272];
    __shared__ float dtile[32][65];
    __shared__ int s_e[32], s_snd[32], s_rcv[32];
    int pb = blockIdx.x*32;
    int tid = threadIdx.x;
    if (tid < 32){
        s_e[tid]  = g_list[pb+tid];
        s_snd[tid]= g_ssnd[pb+tid];
        s_rcv[tid]= g_srcv[pb+tid];
    }
    __syncthreads();
    for (int idx=tid; idx<32*264; idx+=256){
        int e = idx/264, k = idx - e*264;
        float v;
        if (k<8)        v = edge_feats[(size_t)s_e[e]*8 + k];
        else if (k<136) v = g_src[s_snd[e]*128 + (k-8)];
        else            v = g_tgt[s_rcv[e]*128 + (k-136)];
        ef[e][k]=v;
    }
    __syncthreads();
    int o = tid & 63, g = tid >> 6;
    ull aH[8], aD[8];
    #pragma unroll
    for (int i=0;i<8;i++){ aH[i]=0ull; aD[i]=0ull; }
    #pragma unroll 2
    for (int k2=0;k2<132;k2+=2){
        ull wh0=g_pWr0[k2*64+o], wh1=g_pWr0[(k2+1)*64+o];
        ull wd0=g_pWd0[k2*64+o], wd1=g_pWd0[(k2+1)*64+o];
        #pragma unroll
        for (int i=0;i<8;i++){
            const ull* ep = (const ull*)&ef[g*8+i][k2*2];
            ull e0 = ep[0], e1 = ep[1];
            fma2(aH[i], e0, wh0); fma2(aH[i], e1, wh1);
            fma2(aD[i], e0, wd0); fma2(aD[i], e1, wd1);
        }
    }
    #pragma unroll
    for (int i=0;i<8;i++){
        int e = g*8+i;
        g_hA[(size_t)(pb+e)*64 + o] = siluf(red2(aH[i])*IS264);
        dtile[e][o] = siluf(red2(aD[i])*IS264);
    }
    __syncthreads();
    if (tid < 32){
        float acc=0.f;
        for (int k=0;k<64;k++) acc += dtile[tid][k]*Wd1[k];
        acc *= INV8;
        atomicAdd(&g_density[s_rcv[tid]], tanhf(acc*acc));
    }
}

// ---------------- K3: fused hidden x2 + tpw + messages + segmented scatter ----
__global__ __launch_bounds__(512) void k_big(const float* __restrict__ edge_attrs)
{
    __shared__ float ht[32][64];
    __shared__ float hm[32][64];
    __shared__ float ys[32][4];
    __shared__ int s_snd[32], s_rcv[32];
    int pb = blockIdx.x*32;
    int tid = threadIdx.x;
    ((float4*)&ht[0][0])[tid] = ((const float4*)(g_hA + (size_t)pb*64))[tid];
    if (tid < 32){ s_snd[tid]=g_ssnd[pb+tid]; s_rcv[tid]=g_srcv[pb+tid]; }
    if (tid >= 128 && tid < 256){
        int t = tid-128;
        ys[t>>2][t&3] = edge_attrs[(size_t)g_list[pb+(t>>2)]*4 + (t&3)];
    }
    __syncthreads();

    int o = tid & 63, g = tid >> 6;   // 8 groups x 4 edges
    {
        ull acc[4]={0ull,0ull,0ull,0ull};
        for (int k2=0;k2<32;k2+=2){
            ull w0=g_pW1[k2*64+o], w1=g_pW1[(k2+1)*64+o];
            #pragma unroll
            for (int i=0;i<4;i++){
                const ull* hp=(const ull*)&ht[g*4+i][k2*2];
                fma2(acc[i], hp[0], w0); fma2(acc[i], hp[1], w1);
            }
        }
        __syncthreads();
        #pragma unroll
        for (int i=0;i<4;i++) hm[g*4+i][o] = siluf(red2(acc[i])*INV8);
    }
    __syncthreads();
    {
        ull acc[4]={0ull,0ull,0ull,0ull};
        for (int k2=0;k2<32;k2+=2){
            ull w0=g_pW2[k2*64+o], w1=g_pW2[(k2+1)*64+o];
            #pragma unroll
            for (int i=0;i<4;i++){
                const ull* hp=(const ull*)&hm[g*4+i][k2*2];
                fma2(acc[i], hp[0], w0); fma2(acc[i], hp[1], w1);
            }
        }
        __syncthreads();
        #pragma unroll
        for (int i=0;i<4;i++) ht[g*4+i][o] = siluf(red2(acc[i])*INV8);  // h2
    }
    __syncthreads();

    // tpw GEMM + messages + segmented scatter (two passes of 4 edges)
    int w = tid & 127, gg = tid >> 7;   // 4 groups x 8 edges
    float s0=0.f,s1=0.f, va0=0.f,va1=0.f,va2=0.f, vb0=0.f,vb1=0.f,vb2=0.f;
    int cur = s_rcv[gg*8];
    #pragma unroll
    for (int p=0;p<2;p++){
        ull a1[4],a2[4],a3[4],a4[4];
        #pragma unroll
        for (int i=0;i<4;i++){ a1[i]=0ull;a2[i]=0ull;a3[i]=0ull;a4[i]=0ull; }
        int eb0 = gg*8 + p*4;
        #pragma unroll 4
        for (int k2=0;k2<32;k2++){
            const ull* pw = g_pWr3 + k2*512 + w;
            ull w1v=pw[0], w2v=pw[128], w3v=pw[256], w4v=pw[384];
            #pragma unroll
            for (int i=0;i<4;i++){
                ull h2v = *(const ull*)&ht[eb0+i][k2*2];
                fma2(a1[i], h2v, w1v); fma2(a2[i], h2v, w2v);
                fma2(a3[i], h2v, w3v); fma2(a4[i], h2v, w4v);
            }
        }
        #pragma unroll
        for (int i=0;i<4;i++){
            int idx2 = eb0+i;
            int rc = s_rcv[idx2];
            if (rc != cur){
                atomicAdd(&g_msgs[cur*256 + w],       s0);
                atomicAdd(&g_msgs[cur*256 + 128 + w], s1);
                float* pv = &g_msgv[cur*768 + w*3];
                atomicAdd(pv+0,va0);   atomicAdd(pv+1,va1);   atomicAdd(pv+2,va2);
                atomicAdd(pv+384,vb0); atomicAdd(pv+385,vb1); atomicAdd(pv+386,vb2);
                s0=s1=va0=va1=va2=vb0=vb1=vb2=0.f;
                cur = rc;
            }
            int sn = s_snd[idx2];
            float y0=ys[idx2][0], ya=ys[idx2][1], yb=ys[idx2][2], yc=ys[idx2][3];
            float w1f=red2(a1[i])*INV8, w2f=red2(a2[i])*S3, w3f=red2(a3[i])*S3, w4f=red2(a4[i])*S3;
            float xs = g_us[sn*128+w];
            const float* uvp = g_uv + sn*384 + w*3;
            float xv0=uvp[0], xv1=uvp[1], xv2=uvp[2];
            s0 += w1f*xs*y0;
            s1 += w4f*(xv0*ya + xv1*yb + xv2*yc);
            float t2 = w2f*xs;
            va0 += t2*ya; va1 += t2*yb; va2 += t2*yc;
            float t3 = w3f*y0;
            vb0 += t3*xv0; vb1 += t3*xv1; vb2 += t3*xv2;
        }
    }
    atomicAdd(&g_msgs[cur*256 + w],       s0);
    atomicAdd(&g_msgs[cur*256 + 128 + w], s1);
    float* pv = &g_msgv[cur*768 + w*3];
    atomicAdd(pv+0,va0);   atomicAdd(pv+1,va1);   atomicAdd(pv+2,va2);
    atomicAdd(pv+384,vb0); atomicAdd(pv+385,vb1); atomicAdd(pv+386,vb2);
}

// ---------------- K6: node finalize (8 nodes / block) ----------------
__global__ __launch_bounds__(256) void k6_node_out(
    const float* __restrict__ W1v, const float* __restrict__ Wrv,
    const float* __restrict__ W2s, const float* __restrict__ W2v,
    const float* __restrict__ alpha, const float* __restrict__ beta,
    float* __restrict__ out)
{
    __shared__ float ms[8][256];
    __shared__ float mv[8][768];
    __shared__ float su[8][128];
    __shared__ float uvv[8][384];
    __shared__ float rs[8][256];
    __shared__ float rv[8][384];
    __shared__ float sden[8];
    int nb = blockIdx.x*8;
    int tid = threadIdx.x;
    for (int i=tid; i<8*256/4; i+=256) ((float4*)&ms[0][0])[i]  = ((const float4*)(g_msgs + (size_t)nb*256))[i];
    for (int i=tid; i<8*768/4; i+=256) ((float4*)&mv[0][0])[i]  = ((const float4*)(g_msgv + (size_t)nb*768))[i];
    for (int i=tid; i<8*128/4; i+=256) ((float4*)&su[0][0])[i]  = ((const float4*)(g_us   + (size_t)nb*128))[i];
    for (int i=tid; i<8*384/4; i+=256) ((float4*)&uvv[0][0])[i] = ((const float4*)(g_uv   + (size_t)nb*384))[i];
    if (tid<8) sden[tid] = g_density[nb+tid]*beta[0] + alpha[0];
    __syncthreads();

    // m_s: packed f32x2 dot products
    {
        int j = tid;
        ull acc2[8], accr2[8];
        #pragma unroll
        for (int i=0;i<8;i++){ acc2[i]=0ull; accr2[i]=0ull; }
        for (int k2=0;k2<128;k2+=2){
            ull w0=g_pW1s[k2*256+j], w1=g_pW1s[(k2+1)*256+j];
            #pragma unroll
            for (int i=0;i<8;i++){
                const ull* mp=(const ull*)&ms[i][k2*2];
                fma2(acc2[i], mp[0], w0); fma2(acc2[i], mp[1], w1);
            }
        }
        for (int k2=0;k2<64;k2+=2){
            ull w0=g_pWrs[k2*256+j], w1=g_pWrs[(k2+1)*256+j];
            #pragma unroll
            for (int i=0;i<8;i++){
                const ull* sp=(const ull*)&su[i][k2*2];
                fma2(accr2[i], sp[0], w0); fma2(accr2[i], sp[1], w1);
            }
        }
        #pragma unroll
        for (int i=0;i<8;i++) rs[i][j] = red2(acc2[i])*IS256/sden[i] + red2(accr2[i])*IS128;
    }

    // m_v (strided einsum, scalar/float4)
    int w = tid&127, half = tid>>7;
    {
        float av[4][3], ar[4][3];
        #pragma unroll
        for (int i=0;i<4;i++){ av[i][0]=av[i][1]=av[i][2]=0.f; ar[i][0]=ar[i][1]=ar[i][2]=0.f; }
        for (int k=0;k<256;k+=4){
            float wv[4];
            #pragma unroll
            for (int kk=0;kk<4;kk++) wv[kk]=W1v[(k+kk)*128+w];
            #pragma unroll
            for (int i=0;i<4;i++){
                int node = half*4+i;
                float4 a = *(const float4*)&mv[node][k*3];
                float4 b = *(const float4*)&mv[node][k*3+4];
                float4 c = *(const float4*)&mv[node][k*3+8];
                av[i][0]+=a.x*wv[0]+a.w*wv[1]+b.z*wv[2]+c.y*wv[3];
                av[i][1]+=a.y*wv[0]+b.x*wv[1]+b.w*wv[2]+c.z*wv[3];
                av[i][2]+=a.z*wv[0]+b.y*wv[1]+c.x*wv[2]+c.w*wv[3];
            }
        }
        for (int k=0;k<128;k+=4){
            float wv[4];
            #pragma unroll
            for (int kk=0;kk<4;kk++) wv[kk]=Wrv[(k+kk)*128+w];
            #pragma unroll
            for (int i=0;i<4;i++){
                int node = half*4+i;
                float4 a = *(const float4*)&uvv[node][k*3];
                float4 b = *(const float4*)&uvv[node][k*3+4];
                float4 c = *(const float4*)&uvv[node][k*3+8];
                ar[i][0]+=a.x*wv[0]+a.w*wv[1]+b.z*wv[2]+c.y*wv[3];
                ar[i][1]+=a.y*wv[0]+b.x*wv[1]+b.w*wv[2]+c.z*wv[3];
                ar[i][2]+=a.z*wv[0]+b.y*wv[1]+c.x*wv[2]+c.w*wv[3];
            }
        }
        #pragma unroll
        for (int i=0;i<4;i++){
            int node = half*4+i;
            #pragma unroll
            for (int c=0;c<3;c++)
                rv[node][w*3+c] = av[i][c]*IS256/sden[node] + ar[i][c]*IS128;
        }
    }
    __syncthreads();
    {
        int j = tid;
        #pragma unroll
        for (int i=0;i<8;i++){
            float x = rs[i][j];
            float sg = sigmf(x);
            rs[i][j] = (j<128) ? x*sg : sg;
        }
    }
    __syncthreads();
    for (int idx=tid; idx<8*384; idx+=256){
        int i = idx/384, r = idx%384;
        rv[i][r] *= rs[i][128 + r/3];
    }
    __syncthreads();
    {
        float fs[4];
        float fv[4][3];
        #pragma unroll
        for (int i=0;i<4;i++){ fs[i]=0.f; fv[i][0]=fv[i][1]=fv[i][2]=0.f; }
        for (int k=0;k<128;k+=4){
            float w2s[4], w2v[4];
            #pragma unroll
            for (int kk=0;kk<4;kk++){ w2s[kk]=W2s[(k+kk)*128+w]; w2v[kk]=W2v[(k+kk)*128+w]; }
            #pragma unroll
            for (int i=0;i<4;i++){
                int node = half*4+i;
                float4 s4 = *(const float4*)&rs[node][k];
                fs[i]+=s4.x*w2s[0]+s4.y*w2s[1]+s4.z*w2s[2]+s4.w*w2s[3];
                float4 a = *(const float4*)&rv[node][k*3];
                float4 b = *(const float4*)&rv[node][k*3+4];
                float4 c = *(const float4*)&rv[node][k*3+8];
                fv[i][0]+=a.x*w2v[0]+a.w*w2v[1]+b.z*w2v[2]+c.y*w2v[3];
                fv[i][1]+=a.y*w2v[0]+b.x*w2v[1]+b.w*w2v[2]+c.z*w2v[3];
                fv[i][2]+=a.z*w2v[0]+b.y*w2v[1]+c.x*w2v[2]+c.w*w2v[3];
            }
        }
        #pragma unroll
        for (int i=0;i<4;i++){
            int n = nb + half*4 + i;
            float4 o4;
            o4.x = fs[i]*IS128;
            o4.y = fv[i][0]*IS128;
            o4.z = fv[i][1]*IS128;
            o4.w = fv[i][2]*IS128;
            ((float4*)out)[(size_t)n*128 + w] = o4;
        }
    }
}

// ---------------- launch ----------------
extern "C" void kernel_launch(void* const* d_in, const int* in_sizes, int n_in,
                              void* d_out, int out_size)
{
    const float* node_attrs = (const float*)d_in[0];
    const float* node_feats = (const float*)d_in[1];
    const float* edge_attrs = (const float*)d_in[2];
    const float* edge_feats = (const float*)d_in[3];
    const int*   eidx       = (const int*)d_in[4];
    const int* snd = eidx;
    const int* rcv = eidx + NE;
    const float* Wss  = (const float*)d_in[5];
    const float* Wsv  = (const float*)d_in[6];
    const float* Wus  = (const float*)d_in[7];
    const float* Wuv  = (const float*)d_in[8];
    const float* Wsrc = (const float*)d_in[9];
    const float* Wtgt = (const float*)d_in[10];
    const float* Wr0  = (const float*)d_in[11];
    const float* Wr1  = (const float*)d_in[12];
    const float* Wr2  = (const float*)d_in[13];
    const float* Wr3  = (const float*)d_in[14];
    const float* Wd0  = (const float*)d_in[15];
    const float* Wd1  = (const float*)d_in[16];
    const float* W1s  = (const float*)d_in[17];
    const float* W1v  = (const float*)d_in[18];
    const float* Wrs  = (const float*)d_in[19];
    const float* Wrv  = (const float*)d_in[20];
    const float* W2s  = (const float*)d_in[21];
    const float* W2v  = (const float*)d_in[22];
    const float* alpha= (const float*)d_in[23];
    const float* beta = (const float*)d_in[24];

    float* out = (float*)d_out;
    float* out_sc = out + (size_t)NN*512;   // second tuple element

    k0_zero<<<NN*768/4/256, 256>>>();
    k_pack_all<<<(102912+255)/256, 256>>>(Wr0, Wd0, Wr1, Wr2, Wr3, W1s, Wrs, Wus, Wss);
    k_hist<<<NE/256, 256>>>(rcv);
    k_scan<<<1, 1024>>>();
    k_fill<<<NE/256, 256>>>(snd, rcv);
    k1_node_prep<<<NN/8, 128>>>(node_attrs, node_feats, Wsv, Wuv, Wsrc, Wtgt, out_sc);
    k2_edge_l0<<<NE/32, 256>>>(edge_feats, Wd1);
    k_big<<<NE/32, 512>>>(edge_attrs);
    k6_node_out<<<NN/8, 256>>>(W1v, Wrv, W2s, W2v, alpha, beta, out);
}

// round 10
// speedup vs baseline: 1.1109x; 1.1109x over previous
#include <cuda_runtime.h>
#include <math.h>

#define NN 8192
#define NE 131072

#define IS128 0.08838834764831845f
#define IS10  0.31622776601683794f
#define IS264 0.06154574548966636f
#define IS256 0.0625f
#define INV8  0.125f
#define INV_SQRT3 0.57735026918962576f
#define S3 (0.125f*0.57735026918962576f)

// ---------------- scratch (no allocation allowed) ----------------
__device__ float g_us[NN*128];
__device__ float g_uv[NN*384];
__device__ float g_src[NN*128];
__device__ float g_tgt[NN*128];
__device__ float g_hA[(size_t)NE*64];
__device__ float g_density[NN];
__device__ float g_msgs[NN*256];
__device__ float g_msgv[NN*768];
__device__ int   g_cnt[NN];
__device__ int   g_cursor[NN];
__device__ int   g_ssnd[NE];     // sorted position -> sender
__device__ int   g_srcv[NE];     // sorted position -> receiver
__device__ float g_ef8[(size_t)NE*8];   // sorted edge_feats
__device__ float g_y4[(size_t)NE*4];    // sorted edge_attrs

__device__ __forceinline__ float siluf(float x){ return x/(1.0f+expf(-x)); }
__device__ __forceinline__ float sigmf(float x){ return 1.0f/(1.0f+expf(-x)); }

// ---------------- K0: zero accumulators + counters ----------------
__global__ void k0_zero(){
    int idx = blockIdx.x*blockDim.x + threadIdx.x;   // grid covers NN*768/4
    float4 z = make_float4(0.f,0.f,0.f,0.f);
    if (idx < NN*256/4) ((float4*)g_msgs)[idx] = z;
    if (idx < NN*768/4) ((float4*)g_msgv)[idx] = z;
    if (idx < NN/4)     ((float4*)g_density)[idx] = z;
    if (idx < NN)       g_cnt[idx] = 0;
}

// ---------------- sort: histogram / scan / fill ----------------
__global__ void k_hist(const int* __restrict__ rcv){
    int e = blockIdx.x*blockDim.x + threadIdx.x;
    if (e < NE) atomicAdd(&g_cnt[rcv[e]], 1);
}

__global__ __launch_bounds__(1024) void k_scan(){
    __shared__ int part[1024];
    int tid = threadIdx.x;
    int base = tid*8;
    int vals[8]; int sum=0;
    #pragma unroll
    for (int i=0;i<8;i++){ vals[i]=g_cnt[base+i]; sum+=vals[i]; }
    part[tid]=sum;
    __syncthreads();
    for (int d=1; d<1024; d<<=1){
        int v = (tid>=d) ? part[tid-d] : 0;
        __syncthreads();
        part[tid] += v;
        __syncthreads();
    }
    int run = part[tid]-sum;   // exclusive
    #pragma unroll
    for (int i=0;i<8;i++){ g_cursor[base+i]=run; run+=vals[i]; }
}

__global__ void k_fill(const int* __restrict__ snd, const int* __restrict__ rcv,
                       const float* __restrict__ edge_feats,
                       const float* __restrict__ edge_attrs){
    int e = blockIdx.x*blockDim.x + threadIdx.x;
    if (e < NE){
        int r = rcv[e];
        int pos = atomicAdd(&g_cursor[r], 1);
        g_ssnd[pos] = snd[e];
        g_srcv[pos] = r;
        const float4* efp = (const float4*)(edge_feats + (size_t)e*8);
        float4* dst = (float4*)(g_ef8 + (size_t)pos*8);
        dst[0] = efp[0]; dst[1] = efp[1];
        ((float4*)g_y4)[pos] = ((const float4*)edge_attrs)[e];
    }
}

// ---------------- K1: node prep (sc, us, uv, src_e, tgt_e) ----------------
__global__ __launch_bounds__(128) void k1_node_prep(
    const float* __restrict__ node_attrs, const float* __restrict__ node_feats,
    const float* __restrict__ Wss, const float* __restrict__ Wsv,
    const float* __restrict__ Wus, const float* __restrict__ Wuv,
    const float* __restrict__ Wsrc, const float* __restrict__ Wtgt,
    float* __restrict__ out_sc)
{
    __shared__ float s8[8][128];
    __shared__ float v8[8][384];
    __shared__ float a8[8][10];
    int nb = blockIdx.x*8;
    int tid = threadIdx.x;
    for (int idx=tid; idx<8*512; idx+=128){
        int i = idx>>9, f = idx&511;
        float v = node_feats[(size_t)(nb+i)*512 + f];
        if (f<128) s8[i][f]=v; else v8[i][f-128]=v;
    }
    for (int idx=tid; idx<80; idx+=128)
        a8[idx/10][idx%10] = node_attrs[(size_t)(nb + idx/10)*10 + (idx%10)];
    __syncthreads();
    int w = tid;
    float acc1[8], acc2[8];

    #pragma unroll
    for (int i=0;i<8;i++){acc1[i]=0.f;acc2[i]=0.f;}
    for (int k=0;k<128;k+=4){
        float wu[4], ws[4];
        #pragma unroll
        for (int kk=0;kk<4;kk++){ wu[kk]=Wus[(k+kk)*128+w]; ws[kk]=Wss[(k+kk)*128+w]; }
        #pragma unroll
        for (int i=0;i<8;i++){
            float4 s4 = *(const float4*)&s8[i][k];
            acc1[i]+=s4.x*wu[0]+s4.y*wu[1]+s4.z*wu[2]+s4.w*wu[3];
            acc2[i]+=s4.x*ws[0]+s4.y*ws[1]+s4.z*ws[2]+s4.w*ws[3];
        }
    }
    #pragma unroll
    for (int i=0;i<8;i++){
        g_us[(nb+i)*128 + w] = acc1[i]*IS128;
        out_sc[(size_t)(nb+i)*512 + w] = acc2[i]*IS128;
    }

    for (int c=0;c<3;c++){
        #pragma unroll
        for (int i=0;i<8;i++){acc1[i]=0.f;acc2[i]=0.f;}
        for (int k=0;k<128;k++){
            float wu = Wuv[k*128+w], ws = Wsv[k*128+w];
            #pragma unroll
            for (int i=0;i<8;i++){ float vv=v8[i][k*3+c]; acc1[i]+=vv*wu; acc2[i]+=vv*ws; }
        }
        #pragma unroll
        for (int i=0;i<8;i++){
            g_uv[(nb+i)*384 + w*3 + c] = acc1[i]*IS128;
            out_sc[(size_t)(nb+i)*512 + 128 + w*3 + c] = acc2[i]*IS128;
        }
    }

    #pragma unroll
    for (int i=0;i<8;i++){acc1[i]=0.f;acc2[i]=0.f;}
    for (int k=0;k<10;k++){
        float w1 = Wsrc[k*128+w], w2 = Wtgt[k*128+w];
        #pragma unroll
        for (int i=0;i<8;i++){ float av=a8[i][k]; acc1[i]+=av*w1; acc2[i]+=av*w2; }
    }
    #pragma unroll
    for (int i=0;i<8;i++){
        g_src[(nb+i)*128+w] = acc1[i]*IS10;
        g_tgt[(nb+i)*128+w] = acc2[i]*IS10;
    }
}

// ---------------- K2: edge layer0 + density (16 edges/thread) ----------------
__global__ __launch_bounds__(128) void k2_edge_l0(
    const float* __restrict__ Wr0, const float* __restrict__ Wd0,
    const float* __restrict__ Wd1)
{
    __shared__ float ef[32][272];     // 272-float row stride (16B aligned)
    __shared__ float dtile[32][65];
    __shared__ int s_snd[32], s_rcv[32];
    int pb = blockIdx.x*32;
    int tid = threadIdx.x;
    if (tid < 32){
        s_snd[tid]= g_ssnd[pb+tid];
        s_rcv[tid]= g_srcv[pb+tid];
    }
    __syncthreads();
    // fully-vectorized tile load: 32 edges x 66 float4
    for (int idx=tid; idx<32*66; idx+=128){
        int e = idx/66, q = idx - e*66;
        float4 v;
        if (q<2)        v = ((const float4*)(g_ef8 + (size_t)(pb+e)*8))[q];
        else if (q<34)  v = ((const float4*)(g_src + (size_t)s_snd[e]*128))[q-2];
        else            v = ((const float4*)(g_tgt + (size_t)s_rcv[e]*128))[q-34];
        *(float4*)&ef[e][q*4] = v;
    }
    __syncthreads();
    int o = tid & 63, g = tid >> 6;   // 2 groups x 16 edges
    float accH[16], accD[16];
    #pragma unroll
    for (int i=0;i<16;i++){accH[i]=0.f;accD[i]=0.f;}
    for (int k=0;k<264;k+=4){
        float wh[4], wd[4];
        #pragma unroll
        for (int kk=0;kk<4;kk++){ wh[kk]=Wr0[(k+kk)*64+o]; wd[kk]=Wd0[(k+kk)*64+o]; }
        #pragma unroll
        for (int i=0;i<16;i++){
            float4 e4 = *(const float4*)&ef[g*16+i][k];
            accH[i]+=e4.x*wh[0]+e4.y*wh[1]+e4.z*wh[2]+e4.w*wh[3];
            accD[i]+=e4.x*wd[0]+e4.y*wd[1]+e4.z*wd[2]+e4.w*wd[3];
        }
    }
    #pragma unroll
    for (int i=0;i<16;i++){
        int e = g*16+i;
        g_hA[(size_t)(pb+e)*64 + o] = siluf(accH[i]*IS264);   // sorted order
        dtile[e][o] = siluf(accD[i]*IS264);
    }
    __syncthreads();
    if (tid < 32){
        float acc=0.f;
        for (int k=0;k<64;k++) acc += dtile[tid][k]*Wd1[k];
        acc *= INV8;
        atomicAdd(&g_density[s_rcv[tid]], tanhf(acc*acc));
    }
}

// ---------------- K3: fused hidden x2 + tpw + messages + segmented scatter ----
__global__ __launch_bounds__(512) void k_big(
    const float* __restrict__ W1, const float* __restrict__ W2,
    const float* __restrict__ Wr3)
{
    __shared__ float ht[32][64];
    __shared__ float hm[32][64];
    __shared__ float ys[32][4];
    __shared__ int s_snd[32], s_rcv[32];
    int pb = blockIdx.x*32;
    int tid = threadIdx.x;
    ((float4*)&ht[0][0])[tid] = ((const float4*)(g_hA + (size_t)pb*64))[tid];
    if (tid < 32){ s_snd[tid]=g_ssnd[pb+tid]; s_rcv[tid]=g_srcv[pb+tid]; }
    if (tid >= 64 && tid < 96){
        int t = tid-64;
        *(float4*)&ys[t][0] = ((const float4*)g_y4)[pb+t];
    }
    __syncthreads();

    int o = tid & 63, g = tid >> 6;   // 8 groups x 4 edges
    {
        float acc[4] = {0,0,0,0};
        for (int k=0;k<64;k+=4){
            float wv[4];
            #pragma unroll
            for (int kk=0;kk<4;kk++) wv[kk]=W1[(k+kk)*64+o];
            #pragma unroll
            for (int i=0;i<4;i++){
                float4 h4 = *(const float4*)&ht[g*4+i][k];
                acc[i]+=h4.x*wv[0]+h4.y*wv[1]+h4.z*wv[2]+h4.w*wv[3];
            }
        }
        __syncthreads();
        #pragma unroll
        for (int i=0;i<4;i++) hm[g*4+i][o] = siluf(acc[i]*INV8);
    }
    __syncthreads();
    {
        float acc[4] = {0,0,0,0};
        for (int k=0;k<64;k+=4){
            float wv[4];
            #pragma unroll
            for (int kk=0;kk<4;kk++) wv[kk]=W2[(k+kk)*64+o];
            #pragma unroll
            for (int i=0;i<4;i++){
                float4 h4 = *(const float4*)&hm[g*4+i][k];
                acc[i]+=h4.x*wv[0]+h4.y*wv[1]+h4.z*wv[2]+h4.w*wv[3];
            }
        }
        __syncthreads();
        #pragma unroll
        for (int i=0;i<4;i++) ht[g*4+i][o] = siluf(acc[i]*INV8);  // h2 overwrites ht
    }
    __syncthreads();

    // tpw GEMM: 64 -> 512  (4 groups x 8 edges)
    int w = tid & 127, gg = tid >> 7;
    float a1[8],a2[8],a3[8],a4[8];
    #pragma unroll
    for (int i=0;i<8;i++){a1[i]=0.f;a2[i]=0.f;a3[i]=0.f;a4[i]=0.f;}
    for (int k=0;k<64;k+=4){
        float w1v[4],w2v[4],w3v[4],w4v[4];
        #pragma unroll
        for (int kk=0;kk<4;kk++){
            const float* wr = Wr3 + (size_t)(k+kk)*512 + w;
            w1v[kk]=wr[0]; w2v[kk]=wr[128]; w3v[kk]=wr[256]; w4v[kk]=wr[384];
        }
        #pragma unroll
        for (int i=0;i<8;i++){
            float4 h4 = *(const float4*)&ht[gg*8+i][k];
            a1[i]+=h4.x*w1v[0]+h4.y*w1v[1]+h4.z*w1v[2]+h4.w*w1v[3];
            a2[i]+=h4.x*w2v[0]+h4.y*w2v[1]+h4.z*w2v[2]+h4.w*w2v[3];
            a3[i]+=h4.x*w3v[0]+h4.y*w3v[1]+h4.z*w3v[2]+h4.w*w3v[3];
            a4[i]+=h4.x*w4v[0]+h4.y*w4v[1]+h4.z*w4v[2]+h4.w*w4v[3];
        }
    }

    // messages + segmented atomic scatter (edges are rcv-sorted)
    float s0=0.f, s1=0.f;
    float va0=0.f,va1=0.f,va2=0.f, vb0=0.f,vb1=0.f,vb2=0.f;
    int cur = s_rcv[gg*8];
    #pragma unroll
    for (int i=0;i<8;i++){
        int idx2 = gg*8+i;
        int rc = s_rcv[idx2];
        if (rc != cur){
            atomicAdd(&g_msgs[cur*256 + w],        s0);
            atomicAdd(&g_msgs[cur*256 + 128 + w],  s1);
            float* pv = &g_msgv[cur*768 + w*3];
            atomicAdd(pv+0,va0);   atomicAdd(pv+1,va1);   atomicAdd(pv+2,va2);
            atomicAdd(pv+384,vb0); atomicAdd(pv+385,vb1); atomicAdd(pv+386,vb2);
            s0=s1=va0=va1=va2=vb0=vb1=vb2=0.f;
            cur = rc;
        }
        int sn = s_snd[idx2];
        float y0=ys[idx2][0], ya=ys[idx2][1], yb=ys[idx2][2], yc=ys[idx2][3];
        float w1=a1[i]*INV8, w2=a2[i]*S3, w3=a3[i]*S3, w4=a4[i]*S3;
        float xs = g_us[sn*128+w];
        const float* uvp = g_uv + sn*384 + w*3;
        float xv0=uvp[0], xv1=uvp[1], xv2=uvp[2];
        s0 += w1*xs*y0;
        s1 += w4*(xv0*ya + xv1*yb + xv2*yc);
        float t2 = w2*xs;
        va0 += t2*ya; va1 += t2*yb; va2 += t2*yc;
        float t3 = w3*y0;
        vb0 += t3*xv0; vb1 += t3*xv1; vb2 += t3*xv2;
    }
    atomicAdd(&g_msgs[cur*256 + w],        s0);
    atomicAdd(&g_msgs[cur*256 + 128 + w],  s1);
    float* pv = &g_msgv[cur*768 + w*3];
    atomicAdd(pv+0,va0);   atomicAdd(pv+1,va1);   atomicAdd(pv+2,va2);
    atomicAdd(pv+384,vb0); atomicAdd(pv+385,vb1); atomicAdd(pv+386,vb2);
}

// ---------------- K6: node finalize (8 nodes / block) ----------------
__global__ __launch_bounds__(256) void k6_node_out(
    const float* __restrict__ W1s, const float* __restrict__ W1v,
    const float* __restrict__ Wrs, const float* __restrict__ Wrv,
    const float* __restrict__ W2s, const float* __restrict__ W2v,
    const float* __restrict__ alpha, const float* __restrict__ beta,
    float* __restrict__ out)
{
    __shared__ float ms[8][256];
    __shared__ float mv[8][768];
    __shared__ float su[8][128];
    __shared__ float uvv[8][384];
    __shared__ float rs[8][256];
    __shared__ float rv[8][384];
    __shared__ float sden[8];
    int nb = blockIdx.x*8;
    int tid = threadIdx.x;
    for (int i=tid; i<8*256/4; i+=256) ((float4*)&ms[0][0])[i]  = ((const float4*)(g_msgs + (size_t)nb*256))[i];
    for (int i=tid; i<8*768/4; i+=256) ((float4*)&mv[0][0])[i]  = ((const float4*)(g_msgv + (size_t)nb*768))[i];
    for (int i=tid; i<8*128/4; i+=256) ((float4*)&su[0][0])[i]  = ((const float4*)(g_us   + (size_t)nb*128))[i];
    for (int i=tid; i<8*384/4; i+=256) ((float4*)&uvv[0][0])[i] = ((const float4*)(g_uv   + (size_t)nb*384))[i];
    if (tid<8) sden[tid] = g_density[nb+tid]*beta[0] + alpha[0];
    __syncthreads();

    {
        int j = tid;
        float acc[8], accr[8];
        #pragma unroll
        for (int i=0;i<8;i++){acc[i]=0.f;accr[i]=0.f;}
        for (int k=0;k<256;k+=4){
            float wv[4];
            #pragma unroll
            for (int kk=0;kk<4;kk++) wv[kk]=W1s[(k+kk)*256+j];
            #pragma unroll
            for (int i=0;i<8;i++){
                float4 m4 = *(const float4*)&ms[i][k];
                acc[i]+=m4.x*wv[0]+m4.y*wv[1]+m4.z*wv[2]+m4.w*wv[3];
            }
        }
        for (int k=0;k<128;k+=4){
            float wv[4];
            #pragma unroll
            for (int kk=0;kk<4;kk++) wv[kk]=Wrs[(k+kk)*256+j];
            #pragma unroll
            for (int i=0;i<8;i++){
                float4 m4 = *(const float4*)&su[i][k];
                accr[i]+=m4.x*wv[0]+m4.y*wv[1]+m4.z*wv[2]+m4.w*wv[3];
            }
        }
        #pragma unroll
        for (int i=0;i<8;i++) rs[i][j] = acc[i]*IS256/sden[i] + accr[i]*IS128;
    }

    int w = tid&127, half = tid>>7;
    {
        float av[4][3], ar[4][3];
        #pragma unroll
        for (int i=0;i<4;i++){ av[i][0]=av[i][1]=av[i][2]=0.f; ar[i][0]=ar[i][1]=ar[i][2]=0.f; }
        for (int k=0;k<256;k+=4){
            float wv[4];
            #pragma unroll
            for (int kk=0;kk<4;kk++) wv[kk]=W1v[(k+kk)*128+w];
            #pragma unroll
            for (int i=0;i<4;i++){
                int node = half*4+i;
                float4 a = *(const float4*)&mv[node][k*3];
                float4 b = *(const float4*)&mv[node][k*3+4];
                float4 c = *(const float4*)&mv[node][k*3+8];
                av[i][0]+=a.x*wv[0]+a.w*wv[1]+b.z*wv[2]+c.y*wv[3];
                av[i][1]+=a.y*wv[0]+b.x*wv[1]+b.w*wv[2]+c.z*wv[3];
                av[i][2]+=a.z*wv[0]+b.y*wv[1]+c.x*wv[2]+c.w*wv[3];
            }
        }
        for (int k=0;k<128;k+=4){
            float wv[4];
            #pragma unroll
            for (int kk=0;kk<4;kk++) wv[kk]=Wrv[(k+kk)*128+w];
            #pragma unroll
            for (int i=0;i<4;i++){
                int node = half*4+i;
                float4 a = *(const float4*)&uvv[node][k*3];
                float4 b = *(const float4*)&uvv[node][k*3+4];
                float4 c = *(const float4*)&uvv[node][k*3+8];
                ar[i][0]+=a.x*wv[0]+a.w*wv[1]+b.z*wv[2]+c.y*wv[3];
                ar[i][1]+=a.y*wv[0]+b.x*wv[1]+b.w*wv[2]+c.z*wv[3];
                ar[i][2]+=a.z*wv[0]+b.y*wv[1]+c.x*wv[2]+c.w*wv[3];
            }
        }
        #pragma unroll
        for (int i=0;i<4;i++){
            int node = half*4+i;
            #pragma unroll
            for (int c=0;c<3;c++)
                rv[node][w*3+c] = av[i][c]*IS256/sden[node] + ar[i][c]*IS128;
        }
    }
    __syncthreads();
    {
        int j = tid;
        #pragma unroll
        for (int i=0;i<8;i++){
            float x = rs[i][j];
            float sg = sigmf(x);
            rs[i][j] = (j<128) ? x*sg : sg;
        }
    }
    __syncthreads();
    for (int idx=tid; idx<8*384; idx+=256){
        int i = idx/384, r = idx%384;
        rv[i][r] *= rs[i][128 + r/3];
    }
    __syncthreads();
    {
        float fs[4];
        float fv[4][3];
        #pragma unroll
        for (int i=0;i<4;i++){ fs[i]=0.f; fv[i][0]=fv[i][1]=fv[i][2]=0.f; }
        for (int k=0;k<128;k+=4){
            float w2s[4], w2v[4];
            #pragma unroll
            for (int kk=0;kk<4;kk++){ w2s[kk]=W2s[(k+kk)*128+w]; w2v[kk]=W2v[(k+kk)*128+w]; }
            #pragma unroll
            for (int i=0;i<4;i++){
                int node = half*4+i;
                float4 s4 = *(const float4*)&rs[node][k];
                fs[i]+=s4.x*w2s[0]+s4.y*w2s[1]+s4.z*w2s[2]+s4.w*w2s[3];
                float4 a = *(const float4*)&rv[node][k*3];
                float4 b = *(const float4*)&rv[node][k*3+4];
                float4 c = *(const float4*)&rv[node][k*3+8];
                fv[i][0]+=a.x*w2v[0]+a.w*w2v[1]+b.z*w2v[2]+c.y*w2v[3];
                fv[i][1]+=a.y*w2v[0]+b.x*w2v[1]+b.w*w2v[2]+c.z*w2v[3];
                fv[i][2]+=a.z*w2v[0]+b.y*w2v[1]+c.x*w2v[2]+c.w*w2v[3];
            }
        }
        #pragma unroll
        for (int i=0;i<4;i++){
            int n = nb + half*4 + i;
            float4 o4;
            o4.x = fs[i]*IS128;
            o4.y = fv[i][0]*IS128;
            o4.z = fv[i][1]*IS128;
            o4.w = fv[i][2]*IS128;
            ((float4*)out)[(size_t)n*128 + w] = o4;
        }
    }
}

// ---------------- launch ----------------
extern "C" void kernel_launch(void* const* d_in, const int* in_sizes, int n_in,
                              void* d_out, int out_size)
{
    const float* node_attrs = (const float*)d_in[0];
    const float* node_feats = (const float*)d_in[1];
    const float* edge_attrs = (const float*)d_in[2];
    const float* edge_feats = (const float*)d_in[3];
    const int*   eidx       = (const int*)d_in[4];
    const int* snd = eidx;
    const int* rcv = eidx + NE;
    const float* Wss  = (const float*)d_in[5];
    const float* Wsv  = (const float*)d_in[6];
    const float* Wus  = (const float*)d_in[7];
    const float* Wuv  = (const float*)d_in[8];
    const float* Wsrc = (const float*)d_in[9];
    const float* Wtgt = (const float*)d_in[10];
    const float* Wr0  = (const float*)d_in[11];
    const float* Wr1  = (const float*)d_in[12];
    const float* Wr2  = (const float*)d_in[13];
    const float* Wr3  = (const float*)d_in[14];
    const float* Wd0  = (const float*)d_in[15];
    const float* Wd1  = (const float*)d_in[16];
    const float* W1s  = (const float*)d_in[17];
    const float* W1v  = (const float*)d_in[18];
    const float* Wrs  = (const float*)d_in[19];
    const float* Wrv  = (const float*)d_in[20];
    const float* W2s  = (const float*)d_in[21];
    const float* W2v  = (const float*)d_in[22];
    const float* alpha= (const float*)d_in[23];
    const float* beta = (const float*)d_in[24];

    float* out = (float*)d_out;
    float* out_sc = out + (size_t)NN*512;   // second tuple element

    k0_zero<<<NN*768/4/256, 256>>>();
    k_hist<<<NE/256, 256>>>(rcv);
    k_scan<<<1, 1024>>>();
    k_fill<<<NE/256, 256>>>(snd, rcv, edge_feats, edge_attrs);
    k1_node_prep<<<NN/8, 128>>>(node_attrs, node_feats, Wss, Wsv, Wus, Wuv, Wsrc, Wtgt, out_sc);
    k2_edge_l0<<<NE/32, 128>>>(Wr0, Wd0, Wd1);
    k_big<<<NE/32, 512>>>(Wr1, Wr2, Wr3);
    k6_node_out<<<NN/8, 256>>>(W1s, W1v, Wrs, Wrv, W2s, W2v, alpha, beta, out);
}